// round 9
// baseline (speedup 1.0000x reference)
#include <cuda_runtime.h>
#include <cuda_fp16.h>
#include <math.h>

#define GS 96
#define GS2 (GS*GS)
#define NP (GS*GS*GS)          // 884736
#define NVIEW 8
#define HIM 256
#define WIM 256
#define IMPLANE (HIM*WIM)      // 65536
#define TILE_CAP 1024          // max bbox pixels cached in smem (8KB)

// Device scratch (no allocation allowed):
__device__ float4 g_latm4[NP];                   // 14.1 MB
__device__ uint2  g_imgh[NVIEW * IMPLANE];       // 4 MB, half4 (r,g,b,0)*0.5+0.5

// ---------------------------------------------------------------------------
// Kernel 0: repack images [n][3][H][W] -> half4 [n][H*W] with 0.5x+0.5
// ---------------------------------------------------------------------------
__global__ void __launch_bounds__(256) prepack_kernel(const float* __restrict__ images)
{
    int idx = blockIdx.x * 256 + threadIdx.x;     // 524288 total
    int n = idx >> 16;
    int o = idx & (IMPLANE - 1);
    const float* bp = images + (size_t)n * 3 * IMPLANE + o;
    float r = __ldg(bp)               * 0.5f + 0.5f;
    float g = __ldg(bp + IMPLANE)     * 0.5f + 0.5f;
    float b = __ldg(bp + 2 * IMPLANE) * 0.5f + 0.5f;
    __half2 rg = __floats2half2_rn(r, g);
    __half2 b0 = __floats2half2_rn(b, 0.f);
    uint2 u;
    u.x = *reinterpret_cast<unsigned*>(&rg);
    u.y = *reinterpret_cast<unsigned*>(&b0);
    g_imgh[idx] = u;
}

__device__ __forceinline__ float3 pix2f(uint2 u)
{
    __half2 a = *reinterpret_cast<__half2*>(&u.x);
    __half2 b = *reinterpret_cast<__half2*>(&u.y);
    float2 rg = __half22float2(a);
    float2 bp = __half22float2(b);
    return make_float3(rg.x, rg.y, bp.x);
}

// ---------------------------------------------------------------------------
// Kernel A: cubic tiling (4x8x8 per block, warp 2x4x4) + per-(block,view)
// smem image tile: block-reduced bbox, coalesced cooperative load, LDS gathers.
// ---------------------------------------------------------------------------
__global__ void __launch_bounds__(256) encode_kernel(
    const float* __restrict__ poses,
    const float* __restrict__ focal,
    const float* __restrict__ cvec,
    const float* __restrict__ dw1, const float* __restrict__ db1,
    const float* __restrict__ dw2, const float* __restrict__ db2,
    const float* __restrict__ dw3, const float* __restrict__ db3,
    float* __restrict__ out_latent,
    float* __restrict__ lat5)
{
    __shared__ float sposes[NVIEW * 16];
    __shared__ float sw1[27], sb1[3], sw2[9], sb2[3], sw3[9], sb3[3];
    __shared__ float sf[3];
    __shared__ unsigned sredmin[8], sredmax[8];
    __shared__ uint2 s_img[TILE_CAP];          // 8 KB
    __shared__ float S[6 * 256];               // 6 KB staging: ch*256+m

    int tid = threadIdx.x;
    if (tid < NVIEW * 16) sposes[tid] = poses[tid];
    if (tid >= 128 && tid < 128 + 27) sw1[tid - 128] = dw1[tid - 128];
    int u = tid - 160;
    if (u >= 0 && u < 3)  sb1[u] = db1[u];
    if (u >= 3 && u < 12) sw2[u - 3] = dw2[u - 3];
    if (u >= 12 && u < 15) sb2[u - 12] = db2[u - 12];
    if (u >= 15 && u < 24) sw3[u - 15] = dw3[u - 15];
    if (u >= 24 && u < 27) sb3[u - 24] = db3[u - 24];
    if (u == 27) sf[0] = focal[0] * 0.5f;
    if (u == 28) sf[1] = cvec[0] * 0.5f;
    if (u == 29) sf[2] = cvec[1] * 0.5f;
    __syncthreads();

    // thread -> (ix, iy, iz) cubic tile
    int lane = tid & 31, w = tid >> 5;
    int lz = lane & 3, ly = (lane >> 2) & 3, lx = lane >> 4;   // 2x4x4
    int wx = w & 1, wy = (w >> 1) & 1, wz = w >> 2;            // 2x2x2
    int bx = blockIdx.x;                  // 3456 = 24(tx) * 12(ty) * 12(tz)
    int tz = bx % 12;
    int ty = (bx / 12) % 12;
    int tx = bx / 144;
    int jx = wx * 2 + lx;
    int jy = wy * 4 + ly;
    int jz = wz * 4 + lz;
    int ix = tx * 4 + jx;
    int iy = ty * 8 + jy;
    int iz = tz * 8 + jz;
    int p  = (ix * GS + iy) * GS + iz;
    int m  = (jx * 8 + jy) * 8 + jz;      // z-major in-tile index

    float wxp = -1.0f + 2.0f * (float)ix / 95.0f;
    float wyp = -1.0f + 2.0f * (float)iy / 95.0f;
    float wzp = (float)iz / 95.0f;

    const float f   = sf[0];
    const float cx2 = sf[1];
    const float cy2 = sf[2];

    // coalesced store index for out_latent (value index == output index)
    int r8  = tid >> 3, o8 = tid & 7;
    int ojx = r8 >> 3, ojy = r8 & 7;
    size_t olat_off = ((size_t)(tx * 4 + ojx) * GS + ty * 8 + ojy) * GS + tz * 8 + o8;

    float acc0 = 0.f, acc1 = 0.f, acc2 = 0.f;

    #pragma unroll 1
    for (int n = 0; n < NVIEW; n++) {
        const float* Pn = sposes + n * 16;
        float dx = wxp - Pn[3];
        float dy = wyp - Pn[7];
        float dz = wzp - Pn[11];
        float camx = dx * Pn[0] + dy * Pn[4] + dz * Pn[8];
        float camy = dx * Pn[1] + dy * Pn[5] + dz * Pn[9];
        float camz = dx * Pn[2] + dy * Pn[6] + dz * Pn[10];

        const float eps = 1e-9f;
        float ddx = dx + eps, ddy = dy + eps, ddz = dz + eps;
        float invdn = rsqrtf(ddx * ddx + ddy * ddy + ddz * ddz);
        float dirx = dx * invdn, diry = dy * invdn, dirz = dz * invdn;

        float invz = __fdividef(1.0f, camz);
        float uvx =  camx * invz * f + cx2;
        float uvy = -camy * invz * f + cy2;
        float gxn = uvx * (2.0f / 127.0f) - 1.0f;
        float gyn = uvy * (2.0f / 127.0f) - 1.0f;

        bool maskz  = camz < 0.001f;
        bool inside = (fabsf(gxn) <= 1.0f) && (fabsf(gyn) <= 1.0f) && maskz;

        // bilinear coords (valid only when inside)
        float sx = (gxn + 1.0f) * 127.5f;
        float sy = (gyn + 1.0f) * 127.5f;
        float x0f = floorf(sx), y0f = floorf(sy);
        float fx = sx - x0f, fy = sy - y0f;
        int x0 = (int)x0f, y0 = (int)y0f;

        // ---- block bbox reduce (packed u16x2 min/max over warp, then smem) ----
        unsigned pk   = inside ? ((unsigned)x0 | ((unsigned)y0 << 16)) : 0u;
        unsigned pmin = inside ? pk : 0x00FF00FFu;
        unsigned pmax = pk;
        #pragma unroll
        for (int off = 16; off > 0; off >>= 1) {
            pmin = __vminu2(pmin, __shfl_xor_sync(0xffffffffu, pmin, off));
            pmax = __vmaxu2(pmax, __shfl_xor_sync(0xffffffffu, pmax, off));
        }
        if (lane == 0) { sredmin[w] = pmin; sredmax[w] = pmax; }
        int anyb = __syncthreads_or(inside ? 1 : 0);      // sync #1

        float l0 = 0.f, l1 = 0.f, l2 = 0.f;
        bool use_tile = false;
        int X0 = 0, Y0 = 0, Wd = 0;
        if (anyb) {
            unsigned amin = 0x00FF00FFu, amax = 0u;
            #pragma unroll
            for (int k = 0; k < 8; k++) {
                amin = __vminu2(amin, sredmin[k]);
                amax = __vmaxu2(amax, sredmax[k]);
            }
            X0 = (int)(amin & 0xFFFFu);
            Y0 = (int)(amin >> 16);
            int X1 = min((int)(amax & 0xFFFFu) + 1, WIM - 1);
            int Y1 = min((int)(amax >> 16) + 1, HIM - 1);
            Wd = X1 - X0 + 1;
            int Hd = Y1 - Y0 + 1;
            int area = Wd * Hd;
            use_tile = (area <= TILE_CAP);

            if (use_tile) {
                const uint2* base = g_imgh + (size_t)n * IMPLANE;
                for (int r = w; r < Hd; r += 8) {
                    const uint2* rowp = base + ((Y0 + r) << 8) + X0;
                    uint2* srow = s_img + r * Wd;
                    for (int c = lane; c < Wd; c += 32)
                        srow[c] = __ldg(rowp + c);
                }
            }
        }
        __syncthreads();                                   // sync #2: tile ready

        if (inside) {
            int x1 = min(x0 + 1, WIM - 1);
            int y1 = min(y0 + 1, HIM - 1);
            float w00 = (1.f - fx) * (1.f - fy);
            float w01 = fx * (1.f - fy);
            float w10 = (1.f - fx) * fy;
            float w11 = fx * fy;
            float3 v00, v01, v10, v11;
            if (use_tile) {
                int xa = x0 - X0, xb = x1 - X0;
                int ya = (y0 - Y0) * Wd, yb = (y1 - Y0) * Wd;
                v00 = pix2f(s_img[ya + xa]);
                v01 = pix2f(s_img[ya + xb]);
                v10 = pix2f(s_img[yb + xa]);
                v11 = pix2f(s_img[yb + xb]);
            } else {
                const uint2* base = g_imgh + (size_t)n * IMPLANE;
                v00 = pix2f(__ldg(base + (y0 << 8) + x0));
                v01 = pix2f(__ldg(base + (y0 << 8) + x1));
                v10 = pix2f(__ldg(base + (y1 << 8) + x0));
                v11 = pix2f(__ldg(base + (y1 << 8) + x1));
            }
            l0 = v00.x * w00 + v01.x * w01 + v10.x * w10 + v11.x * w11;
            l1 = v00.y * w00 + v01.y * w01 + v10.y * w10 + v11.y * w11;
            l2 = v00.z * w00 + v01.z * w01 + v10.z * w10 + v11.z * w11;
        }

        float mz = maskz ? 1.0f : 0.0f;
        dirx *= mz; diry *= mz; dirz *= mz;

        float xin[9] = { l0, l1, l2, camx, camy, camz, dirx, diry, dirz };
        float h1[3], h2[3], h3[3];
        #pragma unroll
        for (int i = 0; i < 3; i++) {
            float s = sb1[i];
            #pragma unroll
            for (int j = 0; j < 9; j++) s += xin[j] * sw1[i * 9 + j];
            h1[i] = fmaxf(s, 0.0f);
        }
        #pragma unroll
        for (int i = 0; i < 3; i++) {
            float s = sb2[i];
            #pragma unroll
            for (int j = 0; j < 3; j++) s += h1[j] * sw2[i * 3 + j];
            h2[i] = fmaxf(s, 0.0f);
        }
        #pragma unroll
        for (int i = 0; i < 3; i++) {
            float s = sb3[i];
            #pragma unroll
            for (int j = 0; j < 3; j++) s += h2[j] * sw3[i * 3 + j];
            h3[i] = s;
        }

        // stage outputs
        S[0 * 256 + m] = l0;
        S[1 * 256 + m] = l1;
        S[2 * 256 + m] = l2;
        S[3 * 256 + m] = h3[0];
        S[4 * 256 + m] = h3[1];
        S[5 * 256 + m] = h3[2];

        acc0 += h3[0]; acc1 += h3[1]; acc2 += h3[2];

        __syncthreads();                                   // sync #3

        // out_latent[n][c][p]: fully coalesced
        #pragma unroll
        for (int c = 0; c < 3; c++)
            out_latent[((size_t)n * 3 + c) * NP + olat_off] = S[c * 256 + tid];

        // lat5[n][p][c]: 96B-dense runs
        {
            float* dstbase = lat5 + (size_t)n * NP * 3;
            #pragma unroll
            for (int k = 0; k < 3; k++) {
                int j = k * 256 + tid;
                int r = j / 24;
                int o = j % 24;
                int c = o % 3, zz = o / 3;
                int rjx = r >> 3, rjy = r & 7;
                size_t runbase =
                    ((size_t)((tx * 4 + rjx) * GS + (ty * 8 + rjy)) * GS + tz * 8) * 3;
                dstbase[runbase + o] = S[(3 + c) * 256 + r * 8 + zz];
            }
        }
    }

    g_latm4[p] = make_float4(acc0 * 0.125f, acc1 * 0.125f, acc2 * 0.125f, 0.f);
}

// ---------------------------------------------------------------------------
// Kernel B: softmax aggregation (unchanged).
// ---------------------------------------------------------------------------
__global__ void __launch_bounds__(256) agg_kernel(
    const float* __restrict__ ayz_w1, const float* __restrict__ ayz_b1,
    const float* __restrict__ ayz_w2, const float* __restrict__ ayz_b2,
    const float* __restrict__ axz_w1, const float* __restrict__ axz_b1,
    const float* __restrict__ axz_w2, const float* __restrict__ axz_b2,
    const float* __restrict__ axy_w1, const float* __restrict__ axy_b1,
    const float* __restrict__ axy_w2, const float* __restrict__ axy_b2,
    float* __restrict__ out)
{
    int lane = threadIdx.x & 31;
    int wib  = threadIdx.x >> 5;

    if (blockIdx.x < 144) {
        __shared__ float sm[4][32][6];
        int pairid = blockIdx.x * 4 + (wib >> 1);
        int half   = wib & 1;
        int axis = pairid / 288;
        int idx  = pairid % 288;
        int a    = idx / 3;
        int z    = (idx % 3) * 32 + lane;

        const float* W1; const float* B1; const float* W2; const float* B2;
        if (axis == 0) { W1 = ayz_w1; B1 = ayz_b1; W2 = ayz_w2; B2 = ayz_b2; }
        else           { W1 = axz_w1; B1 = axz_b1; W2 = axz_w2; B2 = axz_b2; }

        float w1r[12], b1r[3], w2r[3], b2r;
        #pragma unroll
        for (int i = 0; i < 12; i++) w1r[i] = __ldg(W1 + i);
        #pragma unroll
        for (int i = 0; i < 3; i++)  b1r[i] = __ldg(B1 + i);
        #pragma unroll
        for (int i = 0; i < 3; i++)  w2r[i] = __ldg(W2 + i);
        b2r = __ldg(B2);

        float M = -1e30f, D = 0.f;
        float ac0 = 0.f, ac1 = 0.f, ac2 = 0.f;

        int ebeg = half * 48;
        #pragma unroll 1
        for (int e0 = ebeg; e0 < ebeg + 48; e0 += 4) {
            float4 mv[4]; float sc[4];
            #pragma unroll
            for (int k = 0; k < 4; k++) {
                int e = e0 + k;
                int pp = (axis == 0) ? (e * GS + a) * GS + z
                                     : (a * GS + e) * GS + z;
                mv[k] = __ldg(&g_latm4[pp]);
            }
            #pragma unroll
            for (int k = 0; k < 4; k++) {
                int e = e0 + k;
                float coord = -1.0f + 2.0f * (float)e / 95.0f;
                float s = b2r;
                #pragma unroll
                for (int i = 0; i < 3; i++) {
                    float h = w1r[i*4+0] * mv[k].x + w1r[i*4+1] * mv[k].y +
                              w1r[i*4+2] * mv[k].z + w1r[i*4+3] * coord + b1r[i];
                    s += fmaxf(h, 0.0f) * w2r[i];
                }
                sc[k] = s;
            }
            float bm = fmaxf(fmaxf(sc[0], sc[1]), fmaxf(sc[2], sc[3]));
            float Mn = fmaxf(M, bm);
            float scale = __expf(M - Mn);
            float w0 = __expf(sc[0] - Mn), w1 = __expf(sc[1] - Mn);
            float w2 = __expf(sc[2] - Mn), w3 = __expf(sc[3] - Mn);
            D   = D   * scale + (w0 + w1 + w2 + w3);
            ac0 = ac0 * scale + w0*mv[0].x + w1*mv[1].x + w2*mv[2].x + w3*mv[3].x;
            ac1 = ac1 * scale + w0*mv[0].y + w1*mv[1].y + w2*mv[2].y + w3*mv[3].y;
            ac2 = ac2 * scale + w0*mv[0].z + w1*mv[1].z + w2*mv[2].z + w3*mv[3].z;
            M = Mn;
        }

        int pr = wib >> 1;
        if (half == 1) {
            sm[pr][lane][0] = M;  sm[pr][lane][1] = D;
            sm[pr][lane][2] = ac0; sm[pr][lane][3] = ac1; sm[pr][lane][4] = ac2;
        }
        __syncthreads();
        if (half == 0) {
            float Mb = sm[pr][lane][0], Db = sm[pr][lane][1];
            float b0 = sm[pr][lane][2], b1 = sm[pr][lane][3], b2 = sm[pr][lane][4];
            float Mn = fmaxf(M, Mb);
            float sa = __expf(M - Mn), sb = __expf(Mb - Mn);
            float Dt = D * sa + Db * sb;
            float f0 = ac0 * sa + b0 * sb;
            float f1 = ac1 * sa + b1 * sb;
            float f2 = ac2 * sa + b2 * sb;
            float inv = __fdividef(1.0f, Dt);
            float* dst = out + (axis == 0 ? 2 * 27648 : 0);
            dst[0 * GS2 + a * GS + z] = f0 * inv;
            dst[1 * GS2 + a * GS + z] = f1 * inv;
            dst[2 * GS2 + a * GS + z] = f2 * inv;
        }
    } else {
        int gw2 = (blockIdx.x - 144) * 8 + wib;   // 0..9215
        int a = gw2 / GS;
        int b = gw2 % GS;

        float w1r[12], b1r[3], w2r[3], b2r;
        #pragma unroll
        for (int i = 0; i < 12; i++) w1r[i] = __ldg(axy_w1 + i);
        #pragma unroll
        for (int i = 0; i < 3; i++)  b1r[i] = __ldg(axy_b1 + i);
        #pragma unroll
        for (int i = 0; i < 3; i++)  w2r[i] = __ldg(axy_w2 + i);
        b2r = __ldg(axy_b2);

        float lm[3][3];
        float sc[3];
        int pbase = (a * GS + b) * GS;
        #pragma unroll
        for (int k = 0; k < 3; k++) {
            int e = lane * 3 + k;
            float coord = (float)e / 95.0f;
            float4 m = __ldg(&g_latm4[pbase + e]);
            lm[k][0] = m.x; lm[k][1] = m.y; lm[k][2] = m.z;
            float s = b2r;
            #pragma unroll
            for (int i = 0; i < 3; i++) {
                float h = w1r[i*4+0] * m.x + w1r[i*4+1] * m.y +
                          w1r[i*4+2] * m.z + w1r[i*4+3] * coord + b1r[i];
                s += fmaxf(h, 0.0f) * w2r[i];
            }
            sc[k] = s;
        }

        float m = fmaxf(sc[0], fmaxf(sc[1], sc[2]));
        #pragma unroll
        for (int off = 16; off > 0; off >>= 1)
            m = fmaxf(m, __shfl_xor_sync(0xffffffffu, m, off));
        float e0 = __expf(sc[0] - m), e1 = __expf(sc[1] - m), e2 = __expf(sc[2] - m);
        float ssum = e0 + e1 + e2;
        #pragma unroll
        for (int off = 16; off > 0; off >>= 1)
            ssum += __shfl_xor_sync(0xffffffffu, ssum, off);
        float inv = __fdividef(1.0f, ssum);

        float fl[3];
        #pragma unroll
        for (int c = 0; c < 3; c++) {
            float acc = lm[0][c] * e0 + lm[1][c] * e1 + lm[2][c] * e2;
            #pragma unroll
            for (int off = 16; off > 0; off >>= 1)
                acc += __shfl_xor_sync(0xffffffffu, acc, off);
            fl[c] = acc * inv;
        }

        if (lane == 0) {
            float* dst = out + 27648;
            #pragma unroll
            for (int c = 0; c < 3; c++)
                dst[c * GS2 + a * GS + b] = fl[c];
        }
    }
}

extern "C" void kernel_launch(void* const* d_in, const int* in_sizes, int n_in,
                              void* d_out, int out_size)
{
    const float* images = (const float*)d_in[0];
    const float* poses  = (const float*)d_in[1];
    const float* focal  = (const float*)d_in[2];
    const float* cvec   = (const float*)d_in[3];
    const float* dw1 = (const float*)d_in[4];
    const float* db1 = (const float*)d_in[5];
    const float* dw2 = (const float*)d_in[6];
    const float* db2 = (const float*)d_in[7];
    const float* dw3 = (const float*)d_in[8];
    const float* db3 = (const float*)d_in[9];
    const float* ayz_w1 = (const float*)d_in[10];
    const float* ayz_b1 = (const float*)d_in[11];
    const float* ayz_w2 = (const float*)d_in[12];
    const float* ayz_b2 = (const float*)d_in[13];
    const float* axz_w1 = (const float*)d_in[14];
    const float* axz_b1 = (const float*)d_in[15];
    const float* axz_w2 = (const float*)d_in[16];
    const float* axz_b2 = (const float*)d_in[17];
    const float* axy_w1 = (const float*)d_in[18];
    const float* axy_b1 = (const float*)d_in[19];
    const float* axy_w2 = (const float*)d_in[20];
    const float* axy_b2 = (const float*)d_in[21];

    float* out = (float*)d_out;
    float* out_latent = out + 3 * 27648;
    float* lat5       = out + 3 * 27648 + (size_t)NVIEW * 3 * NP;

    prepack_kernel<<<2048, 256>>>(images);

    encode_kernel<<<3456, 256>>>(poses, focal, cvec,
                                 dw1, db1, dw2, db2, dw3, db3,
                                 out_latent, lat5);

    agg_kernel<<<1296, 256>>>(ayz_w1, ayz_b1, ayz_w2, ayz_b2,
                              axz_w1, axz_b1, axz_w2, axz_b2,
                              axy_w1, axy_b1, axy_w2, axy_b2,
                              out);
}

// round 10
// speedup vs baseline: 1.1559x; 1.1559x over previous
#include <cuda_runtime.h>
#include <cuda_fp16.h>
#include <math.h>

#define GS 96
#define GS2 (GS*GS)
#define NP (GS*GS*GS)          // 884736
#define NVIEW 8
#define HIM 256
#define WIM 256
#define IMPLANE (HIM*WIM)      // 65536

// Device scratch (no allocation allowed):
__device__ float4 g_latm4[NP];                   // 14.1 MB
__device__ uint2  g_imgh[NVIEW * IMPLANE];       // 4 MB, half4 (r,g,b,0)*0.5+0.5

// ---------------------------------------------------------------------------
// Kernel 0: repack images [n][3][H][W] -> half4 [n][H*W] with 0.5x+0.5
// ---------------------------------------------------------------------------
__global__ void __launch_bounds__(256) prepack_kernel(const float* __restrict__ images)
{
    int idx = blockIdx.x * 256 + threadIdx.x;     // 524288 total
    int n = idx >> 16;
    int o = idx & (IMPLANE - 1);
    const float* bp = images + (size_t)n * 3 * IMPLANE + o;
    float r = __ldg(bp)               * 0.5f + 0.5f;
    float g = __ldg(bp + IMPLANE)     * 0.5f + 0.5f;
    float b = __ldg(bp + 2 * IMPLANE) * 0.5f + 0.5f;
    __half2 rg = __floats2half2_rn(r, g);
    __half2 b0 = __floats2half2_rn(b, 0.f);
    uint2 u;
    u.x = *reinterpret_cast<unsigned*>(&rg);
    u.y = *reinterpret_cast<unsigned*>(&b0);
    g_imgh[idx] = u;
}

__device__ __forceinline__ float3 pix2f(uint2 u)
{
    __half2 a = *reinterpret_cast<__half2*>(&u.x);
    __half2 b = *reinterpret_cast<__half2*>(&u.y);
    float2 rg = __half22float2(a);
    float2 bp = __half22float2(b);
    return make_float3(rg.x, rg.y, bp.x);
}

// per-view pipelined state
struct VS {
    float camx, camy, camz;
    float dirx, diry, dirz;
    float fx, fy;
    uint2 q00, q01, q10, q11;
    bool maskz, inside;
};

__device__ __forceinline__ VS stage_view(
    const float* __restrict__ Pn,
    float wxp, float wyp, float wzp,
    float f, float cx2, float cy2, int n)
{
    VS v;
    float dx = wxp - Pn[3];
    float dy = wyp - Pn[7];
    float dz = wzp - Pn[11];
    v.camx = dx * Pn[0] + dy * Pn[4] + dz * Pn[8];
    v.camy = dx * Pn[1] + dy * Pn[5] + dz * Pn[9];
    v.camz = dx * Pn[2] + dy * Pn[6] + dz * Pn[10];

    const float eps = 1e-9f;
    float ddx = dx + eps, ddy = dy + eps, ddz = dz + eps;
    float invdn = rsqrtf(ddx * ddx + ddy * ddy + ddz * ddz);
    v.dirx = dx * invdn; v.diry = dy * invdn; v.dirz = dz * invdn;

    float invz = __fdividef(1.0f, v.camz);
    float uvx =  v.camx * invz * f + cx2;
    float uvy = -v.camy * invz * f + cy2;
    float gxn = uvx * (2.0f / 127.0f) - 1.0f;
    float gyn = uvy * (2.0f / 127.0f) - 1.0f;

    v.maskz  = v.camz < 0.001f;
    v.inside = (fabsf(gxn) <= 1.0f) && (fabsf(gyn) <= 1.0f) && v.maskz;

    uint2 z2; z2.x = 0u; z2.y = 0u;
    v.q00 = z2; v.q01 = z2; v.q10 = z2; v.q11 = z2;
    v.fx = 0.f; v.fy = 0.f;
    if (v.inside) {
        float sx = (gxn + 1.0f) * 127.5f;
        float sy = (gyn + 1.0f) * 127.5f;
        float x0f = floorf(sx), y0f = floorf(sy);
        v.fx = sx - x0f; v.fy = sy - y0f;
        int x0 = (int)x0f, y0 = (int)y0f;
        int x1 = min(x0 + 1, WIM - 1);
        int y1 = min(y0 + 1, HIM - 1);
        const uint2* base = g_imgh + (size_t)n * IMPLANE;
        v.q00 = __ldg(base + (y0 << 8) + x0);
        v.q01 = __ldg(base + (y0 << 8) + x1);
        v.q10 = __ldg(base + (y1 << 8) + x0);
        v.q11 = __ldg(base + (y1 << 8) + x1);
    }
    return v;
}

// ---------------------------------------------------------------------------
// Kernel A: cubic tiling (4x8x8 per block, warp 2x4x4), barrier-free view
// loop with 1-deep software pipeline of the bilinear gathers.
// ---------------------------------------------------------------------------
__global__ void __launch_bounds__(256) encode_kernel(
    const float* __restrict__ poses,
    const float* __restrict__ focal,
    const float* __restrict__ cvec,
    const float* __restrict__ dw1, const float* __restrict__ db1,
    const float* __restrict__ dw2, const float* __restrict__ db2,
    const float* __restrict__ dw3, const float* __restrict__ db3,
    float* __restrict__ out_latent,
    float* __restrict__ lat5)
{
    __shared__ float sposes[NVIEW * 16];
    __shared__ float sw1[27], sb1[3], sw2[9], sb2[3], sw3[9], sb3[3];
    __shared__ float sf[3];

    int tid = threadIdx.x;
    if (tid < NVIEW * 16) sposes[tid] = poses[tid];
    if (tid >= 128 && tid < 128 + 27) sw1[tid - 128] = dw1[tid - 128];
    int u = tid - 160;
    if (u >= 0 && u < 3)  sb1[u] = db1[u];
    if (u >= 3 && u < 12) sw2[u - 3] = dw2[u - 3];
    if (u >= 12 && u < 15) sb2[u - 12] = db2[u - 12];
    if (u >= 15 && u < 24) sw3[u - 15] = dw3[u - 15];
    if (u >= 24 && u < 27) sb3[u - 24] = db3[u - 24];
    if (u == 27) sf[0] = focal[0] * 0.5f;
    if (u == 28) sf[1] = cvec[0] * 0.5f;
    if (u == 29) sf[2] = cvec[1] * 0.5f;
    __syncthreads();

    // thread -> (ix, iy, iz) cubic tile (R7 mapping)
    int lane = tid & 31, w = tid >> 5;
    int lz = lane & 3, ly = (lane >> 2) & 3, lx = lane >> 4;   // 2x4x4
    int wx = w & 1, wy = (w >> 1) & 1, wz = w >> 2;            // 2x2x2
    int bx = blockIdx.x;                  // 3456 = 24(tx) * 12(ty) * 12(tz)
    int tz = bx % 12;
    int ty = (bx / 12) % 12;
    int tx = bx / 144;
    int ix = tx * 4 + wx * 2 + lx;
    int iy = ty * 8 + wy * 4 + ly;
    int iz = tz * 8 + wz * 4 + lz;
    int p  = (ix * GS + iy) * GS + iz;

    float wxp = -1.0f + 2.0f * (float)ix / 95.0f;
    float wyp = -1.0f + 2.0f * (float)iy / 95.0f;
    float wzp = (float)iz / 95.0f;

    const float f   = sf[0];
    const float cx2 = sf[1];
    const float cy2 = sf[2];

    float acc0 = 0.f, acc1 = 0.f, acc2 = 0.f;

    VS cur = stage_view(sposes, wxp, wyp, wzp, f, cx2, cy2, 0);

    #pragma unroll
    for (int n = 0; n < NVIEW; n++) {
        VS nxt;
        if (n + 1 < NVIEW)
            nxt = stage_view(sposes + (n + 1) * 16, wxp, wyp, wzp, f, cx2, cy2, n + 1);

        // consume view n
        float l0 = 0.f, l1 = 0.f, l2 = 0.f;
        if (cur.inside) {
            float w00 = (1.f - cur.fx) * (1.f - cur.fy);
            float w01 = cur.fx * (1.f - cur.fy);
            float w10 = (1.f - cur.fx) * cur.fy;
            float w11 = cur.fx * cur.fy;
            float3 v00 = pix2f(cur.q00);
            float3 v01 = pix2f(cur.q01);
            float3 v10 = pix2f(cur.q10);
            float3 v11 = pix2f(cur.q11);
            l0 = v00.x * w00 + v01.x * w01 + v10.x * w10 + v11.x * w11;
            l1 = v00.y * w00 + v01.y * w01 + v10.y * w10 + v11.y * w11;
            l2 = v00.z * w00 + v01.z * w01 + v10.z * w10 + v11.z * w11;
        }

        float mz = cur.maskz ? 1.0f : 0.0f;
        float dirx = cur.dirx * mz, diry = cur.diry * mz, dirz = cur.dirz * mz;

        float xin[9] = { l0, l1, l2, cur.camx, cur.camy, cur.camz, dirx, diry, dirz };
        float h1[3], h2[3], h3[3];
        #pragma unroll
        for (int i = 0; i < 3; i++) {
            float s = sb1[i];
            #pragma unroll
            for (int j = 0; j < 9; j++) s += xin[j] * sw1[i * 9 + j];
            h1[i] = fmaxf(s, 0.0f);
        }
        #pragma unroll
        for (int i = 0; i < 3; i++) {
            float s = sb2[i];
            #pragma unroll
            for (int j = 0; j < 3; j++) s += h1[j] * sw2[i * 3 + j];
            h2[i] = fmaxf(s, 0.0f);
        }
        #pragma unroll
        for (int i = 0; i < 3; i++) {
            float s = sb3[i];
            #pragma unroll
            for (int j = 0; j < 3; j++) s += h2[j] * sw3[i * 3 + j];
            h3[i] = s;
        }

        // direct stores, no barriers (16B / 48B dense runs)
        out_latent[((size_t)n * 3 + 0) * NP + p] = l0;
        out_latent[((size_t)n * 3 + 1) * NP + p] = l1;
        out_latent[((size_t)n * 3 + 2) * NP + p] = l2;
        size_t lbase = ((size_t)n * NP + p) * 3;
        lat5[lbase + 0] = h3[0];
        lat5[lbase + 1] = h3[1];
        lat5[lbase + 2] = h3[2];

        acc0 += h3[0]; acc1 += h3[1]; acc2 += h3[2];

        cur = nxt;
    }

    g_latm4[p] = make_float4(acc0 * 0.125f, acc1 * 0.125f, acc2 * 0.125f, 0.f);
}

// ---------------------------------------------------------------------------
// Kernel B: softmax aggregation (unchanged — proven since R6).
// ---------------------------------------------------------------------------
__global__ void __launch_bounds__(256) agg_kernel(
    const float* __restrict__ ayz_w1, const float* __restrict__ ayz_b1,
    const float* __restrict__ ayz_w2, const float* __restrict__ ayz_b2,
    const float* __restrict__ axz_w1, const float* __restrict__ axz_b1,
    const float* __restrict__ axz_w2, const float* __restrict__ axz_b2,
    const float* __restrict__ axy_w1, const float* __restrict__ axy_b1,
    const float* __restrict__ axy_w2, const float* __restrict__ axy_b2,
    float* __restrict__ out)
{
    int lane = threadIdx.x & 31;
    int wib  = threadIdx.x >> 5;

    if (blockIdx.x < 144) {
        __shared__ float sm[4][32][6];
        int pairid = blockIdx.x * 4 + (wib >> 1);
        int half   = wib & 1;
        int axis = pairid / 288;
        int idx  = pairid % 288;
        int a    = idx / 3;
        int z    = (idx % 3) * 32 + lane;

        const float* W1; const float* B1; const float* W2; const float* B2;
        if (axis == 0) { W1 = ayz_w1; B1 = ayz_b1; W2 = ayz_w2; B2 = ayz_b2; }
        else           { W1 = axz_w1; B1 = axz_b1; W2 = axz_w2; B2 = axz_b2; }

        float w1r[12], b1r[3], w2r[3], b2r;
        #pragma unroll
        for (int i = 0; i < 12; i++) w1r[i] = __ldg(W1 + i);
        #pragma unroll
        for (int i = 0; i < 3; i++)  b1r[i] = __ldg(B1 + i);
        #pragma unroll
        for (int i = 0; i < 3; i++)  w2r[i] = __ldg(W2 + i);
        b2r = __ldg(B2);

        float M = -1e30f, D = 0.f;
        float ac0 = 0.f, ac1 = 0.f, ac2 = 0.f;

        int ebeg = half * 48;
        #pragma unroll 1
        for (int e0 = ebeg; e0 < ebeg + 48; e0 += 4) {
            float4 mv[4]; float sc[4];
            #pragma unroll
            for (int k = 0; k < 4; k++) {
                int e = e0 + k;
                int pp = (axis == 0) ? (e * GS + a) * GS + z
                                     : (a * GS + e) * GS + z;
                mv[k] = __ldg(&g_latm4[pp]);
            }
            #pragma unroll
            for (int k = 0; k < 4; k++) {
                int e = e0 + k;
                float coord = -1.0f + 2.0f * (float)e / 95.0f;
                float s = b2r;
                #pragma unroll
                for (int i = 0; i < 3; i++) {
                    float h = w1r[i*4+0] * mv[k].x + w1r[i*4+1] * mv[k].y +
                              w1r[i*4+2] * mv[k].z + w1r[i*4+3] * coord + b1r[i];
                    s += fmaxf(h, 0.0f) * w2r[i];
                }
                sc[k] = s;
            }
            float bm = fmaxf(fmaxf(sc[0], sc[1]), fmaxf(sc[2], sc[3]));
            float Mn = fmaxf(M, bm);
            float scale = __expf(M - Mn);
            float w0 = __expf(sc[0] - Mn), w1 = __expf(sc[1] - Mn);
            float w2 = __expf(sc[2] - Mn), w3 = __expf(sc[3] - Mn);
            D   = D   * scale + (w0 + w1 + w2 + w3);
            ac0 = ac0 * scale + w0*mv[0].x + w1*mv[1].x + w2*mv[2].x + w3*mv[3].x;
            ac1 = ac1 * scale + w0*mv[0].y + w1*mv[1].y + w2*mv[2].y + w3*mv[3].y;
            ac2 = ac2 * scale + w0*mv[0].z + w1*mv[1].z + w2*mv[2].z + w3*mv[3].z;
            M = Mn;
        }

        int pr = wib >> 1;
        if (half == 1) {
            sm[pr][lane][0] = M;  sm[pr][lane][1] = D;
            sm[pr][lane][2] = ac0; sm[pr][lane][3] = ac1; sm[pr][lane][4] = ac2;
        }
        __syncthreads();
        if (half == 0) {
            float Mb = sm[pr][lane][0], Db = sm[pr][lane][1];
            float b0 = sm[pr][lane][2], b1 = sm[pr][lane][3], b2 = sm[pr][lane][4];
            float Mn = fmaxf(M, Mb);
            float sa = __expf(M - Mn), sb = __expf(Mb - Mn);
            float Dt = D * sa + Db * sb;
            float f0 = ac0 * sa + b0 * sb;
            float f1 = ac1 * sa + b1 * sb;
            float f2 = ac2 * sa + b2 * sb;
            float inv = __fdividef(1.0f, Dt);
            float* dst = out + (axis == 0 ? 2 * 27648 : 0);
            dst[0 * GS2 + a * GS + z] = f0 * inv;
            dst[1 * GS2 + a * GS + z] = f1 * inv;
            dst[2 * GS2 + a * GS + z] = f2 * inv;
        }
    } else {
        int gw2 = (blockIdx.x - 144) * 8 + wib;   // 0..9215
        int a = gw2 / GS;
        int b = gw2 % GS;

        float w1r[12], b1r[3], w2r[3], b2r;
        #pragma unroll
        for (int i = 0; i < 12; i++) w1r[i] = __ldg(axy_w1 + i);
        #pragma unroll
        for (int i = 0; i < 3; i++)  b1r[i] = __ldg(axy_b1 + i);
        #pragma unroll
        for (int i = 0; i < 3; i++)  w2r[i] = __ldg(axy_w2 + i);
        b2r = __ldg(axy_b2);

        float lm[3][3];
        float sc[3];
        int pbase = (a * GS + b) * GS;
        #pragma unroll
        for (int k = 0; k < 3; k++) {
            int e = lane * 3 + k;
            float coord = (float)e / 95.0f;
            float4 m = __ldg(&g_latm4[pbase + e]);
            lm[k][0] = m.x; lm[k][1] = m.y; lm[k][2] = m.z;
            float s = b2r;
            #pragma unroll
            for (int i = 0; i < 3; i++) {
                float h = w1r[i*4+0] * m.x + w1r[i*4+1] * m.y +
                          w1r[i*4+2] * m.z + w1r[i*4+3] * coord + b1r[i];
                s += fmaxf(h, 0.0f) * w2r[i];
            }
            sc[k] = s;
        }

        float m = fmaxf(sc[0], fmaxf(sc[1], sc[2]));
        #pragma unroll
        for (int off = 16; off > 0; off >>= 1)
            m = fmaxf(m, __shfl_xor_sync(0xffffffffu, m, off));
        float e0 = __expf(sc[0] - m), e1 = __expf(sc[1] - m), e2 = __expf(sc[2] - m);
        float ssum = e0 + e1 + e2;
        #pragma unroll
        for (int off = 16; off > 0; off >>= 1)
            ssum += __shfl_xor_sync(0xffffffffu, ssum, off);
        float inv = __fdividef(1.0f, ssum);

        float fl[3];
        #pragma unroll
        for (int c = 0; c < 3; c++) {
            float acc = lm[0][c] * e0 + lm[1][c] * e1 + lm[2][c] * e2;
            #pragma unroll
            for (int off = 16; off > 0; off >>= 1)
                acc += __shfl_xor_sync(0xffffffffu, acc, off);
            fl[c] = acc * inv;
        }

        if (lane == 0) {
            float* dst = out + 27648;
            #pragma unroll
            for (int c = 0; c < 3; c++)
                dst[c * GS2 + a * GS + b] = fl[c];
        }
    }
}

extern "C" void kernel_launch(void* const* d_in, const int* in_sizes, int n_in,
                              void* d_out, int out_size)
{
    const float* images = (const float*)d_in[0];
    const float* poses  = (const float*)d_in[1];
    const float* focal  = (const float*)d_in[2];
    const float* cvec   = (const float*)d_in[3];
    const float* dw1 = (const float*)d_in[4];
    const float* db1 = (const float*)d_in[5];
    const float* dw2 = (const float*)d_in[6];
    const float* db2 = (const float*)d_in[7];
    const float* dw3 = (const float*)d_in[8];
    const float* db3 = (const float*)d_in[9];
    const float* ayz_w1 = (const float*)d_in[10];
    const float* ayz_b1 = (const float*)d_in[11];
    const float* ayz_w2 = (const float*)d_in[12];
    const float* ayz_b2 = (const float*)d_in[13];
    const float* axz_w1 = (const float*)d_in[14];
    const float* axz_b1 = (const float*)d_in[15];
    const float* axz_w2 = (const float*)d_in[16];
    const float* axz_b2 = (const float*)d_in[17];
    const float* axy_w1 = (const float*)d_in[18];
    const float* axy_b1 = (const float*)d_in[19];
    const float* axy_w2 = (const float*)d_in[20];
    const float* axy_b2 = (const float*)d_in[21];

    float* out = (float*)d_out;
    float* out_latent = out + 3 * 27648;
    float* lat5       = out + 3 * 27648 + (size_t)NVIEW * 3 * NP;

    prepack_kernel<<<2048, 256>>>(images);

    encode_kernel<<<3456, 256>>>(poses, focal, cvec,
                                 dw1, db1, dw2, db2, dw3, db3,
                                 out_latent, lat5);

    agg_kernel<<<1296, 256>>>(ayz_w1, ayz_b1, ayz_w2, ayz_b2,
                              axz_w1, axz_b1, axz_w2, axz_b2,
                              axy_w1, axy_b1, axy_w2, axy_b2,
                              out);
}

// round 11
// speedup vs baseline: 1.2801x; 1.1074x over previous
#include <cuda_runtime.h>
#include <cuda_fp16.h>
#include <math.h>

#define GS 96
#define GS2 (GS*GS)
#define NP (GS*GS*GS)          // 884736
#define NVIEW 8
#define HIM 256
#define WIM 256
#define IMPLANE (HIM*WIM)      // 65536

// Device scratch (no allocation allowed):
__device__ float4 g_latm4[NP];                   // 14.1 MB
__device__ uint2  g_imgh[NVIEW * IMPLANE];       // 4 MB, half4 (r,g,b,0)*0.5+0.5

// ---------------------------------------------------------------------------
// Kernel 0: repack images [n][3][H][W] -> half4 [n][H*W] with 0.5x+0.5
// ---------------------------------------------------------------------------
__global__ void __launch_bounds__(256) prepack_kernel(const float* __restrict__ images)
{
    int idx = blockIdx.x * 256 + threadIdx.x;     // 524288 total
    int n = idx >> 16;
    int o = idx & (IMPLANE - 1);
    const float* bp = images + (size_t)n * 3 * IMPLANE + o;
    float r = __ldg(bp)               * 0.5f + 0.5f;
    float g = __ldg(bp + IMPLANE)     * 0.5f + 0.5f;
    float b = __ldg(bp + 2 * IMPLANE) * 0.5f + 0.5f;
    __half2 rg = __floats2half2_rn(r, g);
    __half2 b0 = __floats2half2_rn(b, 0.f);
    uint2 u;
    u.x = *reinterpret_cast<unsigned*>(&rg);
    u.y = *reinterpret_cast<unsigned*>(&b0);
    g_imgh[idx] = u;
}

__device__ __forceinline__ float3 pix2f(uint2 u)
{
    __half2 a = *reinterpret_cast<__half2*>(&u.x);
    __half2 b = *reinterpret_cast<__half2*>(&u.y);
    float2 rg = __half22float2(a);
    float2 bp = __half22float2(b);
    return make_float3(rg.x, rg.y, bp.x);
}

// per-view pipelined state
struct VS {
    float camx, camy, camz;
    float dirx, diry, dirz;
    float fx, fy;
    uint2 q00, q01, q10, q11;
    bool maskz, inside;
};

__device__ __forceinline__ VS stage_view(
    const float* __restrict__ Pn,
    float wxp, float wyp, float wzp,
    float f, float cx2, float cy2, int n)
{
    VS v;
    float dx = wxp - Pn[3];
    float dy = wyp - Pn[7];
    float dz = wzp - Pn[11];
    v.camx = dx * Pn[0] + dy * Pn[4] + dz * Pn[8];
    v.camy = dx * Pn[1] + dy * Pn[5] + dz * Pn[9];
    v.camz = dx * Pn[2] + dy * Pn[6] + dz * Pn[10];

    const float eps = 1e-9f;
    float ddx = dx + eps, ddy = dy + eps, ddz = dz + eps;
    float invdn = rsqrtf(ddx * ddx + ddy * ddy + ddz * ddz);
    v.dirx = dx * invdn; v.diry = dy * invdn; v.dirz = dz * invdn;

    float invz = __fdividef(1.0f, v.camz);
    float uvx =  v.camx * invz * f + cx2;
    float uvy = -v.camy * invz * f + cy2;
    float gxn = uvx * (2.0f / 127.0f) - 1.0f;
    float gyn = uvy * (2.0f / 127.0f) - 1.0f;

    v.maskz  = v.camz < 0.001f;
    v.inside = (fabsf(gxn) <= 1.0f) && (fabsf(gyn) <= 1.0f) && v.maskz;

    uint2 z2; z2.x = 0u; z2.y = 0u;
    v.q00 = z2; v.q01 = z2; v.q10 = z2; v.q11 = z2;
    v.fx = 0.f; v.fy = 0.f;
    if (v.inside) {
        float sx = (gxn + 1.0f) * 127.5f;
        float sy = (gyn + 1.0f) * 127.5f;
        float x0f = floorf(sx), y0f = floorf(sy);
        v.fx = sx - x0f; v.fy = sy - y0f;
        int x0 = (int)x0f, y0 = (int)y0f;
        int x1 = min(x0 + 1, WIM - 1);
        int y1 = min(y0 + 1, HIM - 1);
        const uint2* base = g_imgh + (size_t)n * IMPLANE;
        v.q00 = __ldg(base + (y0 << 8) + x0);
        v.q01 = __ldg(base + (y0 << 8) + x1);
        v.q10 = __ldg(base + (y1 << 8) + x0);
        v.q11 = __ldg(base + (y1 << 8) + x1);
    }
    return v;
}

// ---------------------------------------------------------------------------
// Kernel A: R7 base (cubic 4x8x8 tile, warp 2x4x4, smem-staged lat5) plus
// 1-deep software pipeline of next view's projection + gathers.
// ---------------------------------------------------------------------------
__global__ void __launch_bounds__(256) encode_kernel(
    const float* __restrict__ poses,
    const float* __restrict__ focal,
    const float* __restrict__ cvec,
    const float* __restrict__ dw1, const float* __restrict__ db1,
    const float* __restrict__ dw2, const float* __restrict__ db2,
    const float* __restrict__ dw3, const float* __restrict__ db3,
    float* __restrict__ out_latent,
    float* __restrict__ lat5)
{
    __shared__ float sposes[NVIEW * 16];
    __shared__ float sw1[27], sb1[3], sw2[9], sb2[3], sw3[9], sb3[3];
    __shared__ float sf[3];
    __shared__ float s_lat5[768];

    int tid = threadIdx.x;
    if (tid < NVIEW * 16) sposes[tid] = poses[tid];
    if (tid >= 128 && tid < 128 + 27) sw1[tid - 128] = dw1[tid - 128];
    int u = tid - 160;
    if (u >= 0 && u < 3)  sb1[u] = db1[u];
    if (u >= 3 && u < 12) sw2[u - 3] = dw2[u - 3];
    if (u >= 12 && u < 15) sb2[u - 12] = db2[u - 12];
    if (u >= 15 && u < 24) sw3[u - 15] = dw3[u - 15];
    if (u >= 24 && u < 27) sb3[u - 24] = db3[u - 24];
    if (u == 27) sf[0] = focal[0] * 0.5f;
    if (u == 28) sf[1] = cvec[0] * 0.5f;
    if (u == 29) sf[2] = cvec[1] * 0.5f;
    __syncthreads();

    // thread -> (ix, iy, iz) cubic tile (R7 mapping)
    int lane = tid & 31, w = tid >> 5;
    int lz = lane & 3, ly = (lane >> 2) & 3, lx = lane >> 4;   // 2x4x4
    int wx = w & 1, wy = (w >> 1) & 1, wz = w >> 2;            // 2x2x2
    int bx = blockIdx.x;                  // 3456 = 24(tx) * 12(ty) * 12(tz)
    int tz = bx % 12;
    int ty = (bx / 12) % 12;
    int tx = bx / 144;
    int jx = wx * 2 + lx;                 // 0..3
    int jy = wy * 4 + ly;                 // 0..7
    int jz = wz * 4 + lz;                 // 0..7
    int ix = tx * 4 + jx;
    int iy = ty * 8 + jy;
    int iz = tz * 8 + jz;
    int p  = (ix * GS + iy) * GS + iz;
    int m  = (jx * 8 + jy) * 8 + jz;      // z-major in-tile index

    float wxp = -1.0f + 2.0f * (float)ix / 95.0f;
    float wyp = -1.0f + 2.0f * (float)iy / 95.0f;
    float wzp = (float)iz / 95.0f;

    const float f   = sf[0];
    const float cx2 = sf[1];
    const float cy2 = sf[2];

    float acc0 = 0.f, acc1 = 0.f, acc2 = 0.f;

    VS cur = stage_view(sposes, wxp, wyp, wzp, f, cx2, cy2, 0);

    #pragma unroll
    for (int n = 0; n < NVIEW; n++) {
        VS nxt;
        if (n + 1 < NVIEW)
            nxt = stage_view(sposes + (n + 1) * 16, wxp, wyp, wzp, f, cx2, cy2, n + 1);

        // consume view n
        float l0 = 0.f, l1 = 0.f, l2 = 0.f;
        if (cur.inside) {
            float w00 = (1.f - cur.fx) * (1.f - cur.fy);
            float w01 = cur.fx * (1.f - cur.fy);
            float w10 = (1.f - cur.fx) * cur.fy;
            float w11 = cur.fx * cur.fy;
            float3 v00 = pix2f(cur.q00);
            float3 v01 = pix2f(cur.q01);
            float3 v10 = pix2f(cur.q10);
            float3 v11 = pix2f(cur.q11);
            l0 = v00.x * w00 + v01.x * w01 + v10.x * w10 + v11.x * w11;
            l1 = v00.y * w00 + v01.y * w01 + v10.y * w10 + v11.y * w11;
            l2 = v00.z * w00 + v01.z * w01 + v10.z * w10 + v11.z * w11;
        }

        float mz = cur.maskz ? 1.0f : 0.0f;
        float dirx = cur.dirx * mz, diry = cur.diry * mz, dirz = cur.dirz * mz;

        float xin[9] = { l0, l1, l2, cur.camx, cur.camy, cur.camz, dirx, diry, dirz };
        float h1[3], h2[3], h3[3];
        #pragma unroll
        for (int i = 0; i < 3; i++) {
            float s = sb1[i];
            #pragma unroll
            for (int j = 0; j < 9; j++) s += xin[j] * sw1[i * 9 + j];
            h1[i] = fmaxf(s, 0.0f);
        }
        #pragma unroll
        for (int i = 0; i < 3; i++) {
            float s = sb2[i];
            #pragma unroll
            for (int j = 0; j < 3; j++) s += h1[j] * sw2[i * 3 + j];
            h2[i] = fmaxf(s, 0.0f);
        }
        #pragma unroll
        for (int i = 0; i < 3; i++) {
            float s = sb3[i];
            #pragma unroll
            for (int j = 0; j < 3; j++) s += h2[j] * sw3[i * 3 + j];
            h3[i] = s;
        }

        // out_latent[n][c][p] — direct (16B-dense runs), as in R7
        out_latent[((size_t)n * 3 + 0) * NP + p] = l0;
        out_latent[((size_t)n * 3 + 1) * NP + p] = l1;
        out_latent[((size_t)n * 3 + 2) * NP + p] = l2;

        // lat5[n][p][c] via smem remap -> 96B-dense runs (R7 scheme)
        s_lat5[m * 3 + 0] = h3[0];
        s_lat5[m * 3 + 1] = h3[1];
        s_lat5[m * 3 + 2] = h3[2];
        __syncthreads();
        {
            float* dstbase = lat5 + (size_t)n * NP * 3;
            #pragma unroll
            for (int k = 0; k < 3; k++) {
                int j = k * 256 + tid;          // 0..767
                int r = j / 24;                 // run = jx*8+jy
                int o = j % 24;                 // offset in 96B run
                int rjx = r >> 3, rjy = r & 7;
                size_t runbase =
                    ((size_t)((tx * 4 + rjx) * GS + (ty * 8 + rjy)) * GS + tz * 8) * 3;
                dstbase[runbase + o] = s_lat5[j];
            }
        }
        __syncthreads();

        acc0 += h3[0]; acc1 += h3[1]; acc2 += h3[2];

        cur = nxt;
    }

    g_latm4[p] = make_float4(acc0 * 0.125f, acc1 * 0.125f, acc2 * 0.125f, 0.f);
}

// ---------------------------------------------------------------------------
// Kernel B: softmax aggregation (unchanged — proven since R6).
// ---------------------------------------------------------------------------
__global__ void __launch_bounds__(256) agg_kernel(
    const float* __restrict__ ayz_w1, const float* __restrict__ ayz_b1,
    const float* __restrict__ ayz_w2, const float* __restrict__ ayz_b2,
    const float* __restrict__ axz_w1, const float* __restrict__ axz_b1,
    const float* __restrict__ axz_w2, const float* __restrict__ axz_b2,
    const float* __restrict__ axy_w1, const float* __restrict__ axy_b1,
    const float* __restrict__ axy_w2, const float* __restrict__ axy_b2,
    float* __restrict__ out)
{
    int lane = threadIdx.x & 31;
    int wib  = threadIdx.x >> 5;

    if (blockIdx.x < 144) {
        __shared__ float sm[4][32][6];
        int pairid = blockIdx.x * 4 + (wib >> 1);
        int half   = wib & 1;
        int axis = pairid / 288;
        int idx  = pairid % 288;
        int a    = idx / 3;
        int z    = (idx % 3) * 32 + lane;

        const float* W1; const float* B1; const float* W2; const float* B2;
        if (axis == 0) { W1 = ayz_w1; B1 = ayz_b1; W2 = ayz_w2; B2 = ayz_b2; }
        else           { W1 = axz_w1; B1 = axz_b1; W2 = axz_w2; B2 = axz_b2; }

        float w1r[12], b1r[3], w2r[3], b2r;
        #pragma unroll
        for (int i = 0; i < 12; i++) w1r[i] = __ldg(W1 + i);
        #pragma unroll
        for (int i = 0; i < 3; i++)  b1r[i] = __ldg(B1 + i);
        #pragma unroll
        for (int i = 0; i < 3; i++)  w2r[i] = __ldg(W2 + i);
        b2r = __ldg(B2);

        float M = -1e30f, D = 0.f;
        float ac0 = 0.f, ac1 = 0.f, ac2 = 0.f;

        int ebeg = half * 48;
        #pragma unroll 1
        for (int e0 = ebeg; e0 < ebeg + 48; e0 += 4) {
            float4 mv[4]; float sc[4];
            #pragma unroll
            for (int k = 0; k < 4; k++) {
                int e = e0 + k;
                int pp = (axis == 0) ? (e * GS + a) * GS + z
                                     : (a * GS + e) * GS + z;
                mv[k] = __ldg(&g_latm4[pp]);
            }
            #pragma unroll
            for (int k = 0; k < 4; k++) {
                int e = e0 + k;
                float coord = -1.0f + 2.0f * (float)e / 95.0f;
                float s = b2r;
                #pragma unroll
                for (int i = 0; i < 3; i++) {
                    float h = w1r[i*4+0] * mv[k].x + w1r[i*4+1] * mv[k].y +
                              w1r[i*4+2] * mv[k].z + w1r[i*4+3] * coord + b1r[i];
                    s += fmaxf(h, 0.0f) * w2r[i];
                }
                sc[k] = s;
            }
            float bm = fmaxf(fmaxf(sc[0], sc[1]), fmaxf(sc[2], sc[3]));
            float Mn = fmaxf(M, bm);
            float scale = __expf(M - Mn);
            float w0 = __expf(sc[0] - Mn), w1 = __expf(sc[1] - Mn);
            float w2 = __expf(sc[2] - Mn), w3 = __expf(sc[3] - Mn);
            D   = D   * scale + (w0 + w1 + w2 + w3);
            ac0 = ac0 * scale + w0*mv[0].x + w1*mv[1].x + w2*mv[2].x + w3*mv[3].x;
            ac1 = ac1 * scale + w0*mv[0].y + w1*mv[1].y + w2*mv[2].y + w3*mv[3].y;
            ac2 = ac2 * scale + w0*mv[0].z + w1*mv[1].z + w2*mv[2].z + w3*mv[3].z;
            M = Mn;
        }

        int pr = wib >> 1;
        if (half == 1) {
            sm[pr][lane][0] = M;  sm[pr][lane][1] = D;
            sm[pr][lane][2] = ac0; sm[pr][lane][3] = ac1; sm[pr][lane][4] = ac2;
        }
        __syncthreads();
        if (half == 0) {
            float Mb = sm[pr][lane][0], Db = sm[pr][lane][1];
            float b0 = sm[pr][lane][2], b1 = sm[pr][lane][3], b2 = sm[pr][lane][4];
            float Mn = fmaxf(M, Mb);
            float sa = __expf(M - Mn), sb = __expf(Mb - Mn);
            float Dt = D * sa + Db * sb;
            float f0 = ac0 * sa + b0 * sb;
            float f1 = ac1 * sa + b1 * sb;
            float f2 = ac2 * sa + b2 * sb;
            float inv = __fdividef(1.0f, Dt);
            float* dst = out + (axis == 0 ? 2 * 27648 : 0);
            dst[0 * GS2 + a * GS + z] = f0 * inv;
            dst[1 * GS2 + a * GS + z] = f1 * inv;
            dst[2 * GS2 + a * GS + z] = f2 * inv;
        }
    } else {
        int gw2 = (blockIdx.x - 144) * 8 + wib;   // 0..9215
        int a = gw2 / GS;
        int b = gw2 % GS;

        float w1r[12], b1r[3], w2r[3], b2r;
        #pragma unroll
        for (int i = 0; i < 12; i++) w1r[i] = __ldg(axy_w1 + i);
        #pragma unroll
        for (int i = 0; i < 3; i++)  b1r[i] = __ldg(axy_b1 + i);
        #pragma unroll
        for (int i = 0; i < 3; i++)  w2r[i] = __ldg(axy_w2 + i);
        b2r = __ldg(axy_b2);

        float lm[3][3];
        float sc[3];
        int pbase = (a * GS + b) * GS;
        #pragma unroll
        for (int k = 0; k < 3; k++) {
            int e = lane * 3 + k;
            float coord = (float)e / 95.0f;
            float4 m = __ldg(&g_latm4[pbase + e]);
            lm[k][0] = m.x; lm[k][1] = m.y; lm[k][2] = m.z;
            float s = b2r;
            #pragma unroll
            for (int i = 0; i < 3; i++) {
                float h = w1r[i*4+0] * m.x + w1r[i*4+1] * m.y +
                          w1r[i*4+2] * m.z + w1r[i*4+3] * coord + b1r[i];
                s += fmaxf(h, 0.0f) * w2r[i];
            }
            sc[k] = s;
        }

        float m = fmaxf(sc[0], fmaxf(sc[1], sc[2]));
        #pragma unroll
        for (int off = 16; off > 0; off >>= 1)
            m = fmaxf(m, __shfl_xor_sync(0xffffffffu, m, off));
        float e0 = __expf(sc[0] - m), e1 = __expf(sc[1] - m), e2 = __expf(sc[2] - m);
        float ssum = e0 + e1 + e2;
        #pragma unroll
        for (int off = 16; off > 0; off >>= 1)
            ssum += __shfl_xor_sync(0xffffffffu, ssum, off);
        float inv = __fdividef(1.0f, ssum);

        float fl[3];
        #pragma unroll
        for (int c = 0; c < 3; c++) {
            float acc = lm[0][c] * e0 + lm[1][c] * e1 + lm[2][c] * e2;
            #pragma unroll
            for (int off = 16; off > 0; off >>= 1)
                acc += __shfl_xor_sync(0xffffffffu, acc, off);
            fl[c] = acc * inv;
        }

        if (lane == 0) {
            float* dst = out + 27648;
            #pragma unroll
            for (int c = 0; c < 3; c++)
                dst[c * GS2 + a * GS + b] = fl[c];
        }
    }
}

extern "C" void kernel_launch(void* const* d_in, const int* in_sizes, int n_in,
                              void* d_out, int out_size)
{
    const float* images = (const float*)d_in[0];
    const float* poses  = (const float*)d_in[1];
    const float* focal  = (const float*)d_in[2];
    const float* cvec   = (const float*)d_in[3];
    const float* dw1 = (const float*)d_in[4];
    const float* db1 = (const float*)d_in[5];
    const float* dw2 = (const float*)d_in[6];
    const float* db2 = (const float*)d_in[7];
    const float* dw3 = (const float*)d_in[8];
    const float* db3 = (const float*)d_in[9];
    const float* ayz_w1 = (const float*)d_in[10];
    const float* ayz_b1 = (const float*)d_in[11];
    const float* ayz_w2 = (const float*)d_in[12];
    const float* ayz_b2 = (const float*)d_in[13];
    const float* axz_w1 = (const float*)d_in[14];
    const float* axz_b1 = (const float*)d_in[15];
    const float* axz_w2 = (const float*)d_in[16];
    const float* axz_b2 = (const float*)d_in[17];
    const float* axy_w1 = (const float*)d_in[18];
    const float* axy_b1 = (const float*)d_in[19];
    const float* axy_w2 = (const float*)d_in[20];
    const float* axy_b2 = (const float*)d_in[21];

    float* out = (float*)d_out;
    float* out_latent = out + 3 * 27648;
    float* lat5       = out + 3 * 27648 + (size_t)NVIEW * 3 * NP;

    prepack_kernel<<<2048, 256>>>(images);

    encode_kernel<<<3456, 256>>>(poses, focal, cvec,
                                 dw1, db1, dw2, db2, dw3, db3,
                                 out_latent, lat5);

    agg_kernel<<<1296, 256>>>(ayz_w1, ayz_b1, ayz_w2, ayz_b2,
                              axz_w1, axz_b1, axz_w2, axz_b2,
                              axy_w1, axy_b1, axy_w2, axy_b2,
                              out);
}